// round 16
// baseline (speedup 1.0000x reference)
#include <cuda_runtime.h>
#include <cstdint>

// Problem constants (match reference setup_inputs)
#define FEAT        128

// Tuning (champion shape: MLP 8/warp, ~40 warps/SM)
#define ROWS_PER_WARP   128
#define WARPS_PER_BLOCK 8
#define BLOCK_THREADS   (WARPS_PER_BLOCK * 32)

// ---------------------------------------------------------------------------
// PDL primitives
// ---------------------------------------------------------------------------
__device__ __forceinline__ void pdl_trigger() {
    asm volatile("griddepcontrol.launch_dependents;" ::: "memory");
}
__device__ __forceinline__ void pdl_wait() {
    asm volatile("griddepcontrol.wait;" ::: "memory");
}

// ---------------------------------------------------------------------------
// Kernel 1 (prologue): zero the output, then signal dependents (PDL).
// ---------------------------------------------------------------------------
__global__ void prologue_kernel(float4* __restrict__ out, int n4) {
    int i = blockIdx.x * blockDim.x + threadIdx.x;
    if (i < n4) out[i] = make_float4(0.f, 0.f, 0.f, 0.f);
    pdl_trigger();
}

// ---------------------------------------------------------------------------
// Kernel 2: sorted segment sum (champion design).
// One warp owns ROWS_PER_WARP contiguous rows; each lane owns 4 features
// (one LDG.128 per row per lane, streaming/evict-first). Sortedness
// shortcut: per 8-row group load only the LAST id; equality with cur implies
// the whole group belongs to one segment -> branch-free tree accumulation.
// atomicAdd flush on segment change / chunk end (chunks can split a segment
// across warps). pdl_wait() is issued lazily before the FIRST flush so the
// 512MB load stream overlaps the prologue's zeroing.
// Dtype detect (int32 vs int64 batch) inline per warp: odd int32 words of
// little-endian int64 (< 2^31) are zero high-halves.
// ---------------------------------------------------------------------------
__device__ __forceinline__ void flush_acc(float* __restrict__ out,
                                          int seg, int lane, const float4& acc,
                                          int max_seg, bool& synced) {
    if (!synced) { pdl_wait(); synced = true; }
    if (seg < 0 || seg >= max_seg) return;  // insurance against bad ids
    float* p = out + (size_t)seg * FEAT + lane * 4;
    atomicAdd(p + 0, acc.x);
    atomicAdd(p + 1, acc.y);
    atomicAdd(p + 2, acc.z);
    atomicAdd(p + 3, acc.w);
}

__global__ __launch_bounds__(BLOCK_THREADS)
void seg_sum_kernel(const float4* __restrict__ h,     // [n_rows][32] float4
                    const int* __restrict__ braw,     // batch, stride words
                    float* __restrict__ out,          // [max_seg][FEAT]
                    int n_rows, int max_seg) {
    const int warp_id = blockIdx.x * WARPS_PER_BLOCK + (threadIdx.x >> 5);
    const int lane    = threadIdx.x & 31;

    // Inline dtype detect (warp-wide ballot over odd tail words).
    int didx = n_rows - 1 - 2 * lane;
    if (!(didx & 1)) didx -= 1;                       // force odd index
    int nz = (didx > 0) ? (braw[didx] != 0) : 0;
    const int stride = __any_sync(0xFFFFFFFF, nz) ? 1 : 2;

    int start = warp_id * ROWS_PER_WARP;
    if (start >= n_rows) return;
    int end = min(start + ROWS_PER_WARP, n_rows);

    bool synced = false;
    float4 acc = make_float4(0.f, 0.f, 0.f, 0.f);
    int cur = braw[start * stride];

    int r = start;
    for (; r + 8 <= end; r += 8) {
        // One warp-uniform index load per 8 rows (sorted => s7==cur covers all)
        int s7 = braw[(r + 7) * stride];

        float4 v[8];
        #pragma unroll
        for (int j = 0; j < 8; ++j)
            v[j] = __ldcs(&h[(size_t)(r + j) * 32 + lane]);

        if (s7 == cur) {
            // Fast path: tree-sum the 8 rows, single dependency on acc.
            float4 t01, t23, t45, t67, t03, t47, t;
            t01.x = v[0].x + v[1].x; t01.y = v[0].y + v[1].y; t01.z = v[0].z + v[1].z; t01.w = v[0].w + v[1].w;
            t23.x = v[2].x + v[3].x; t23.y = v[2].y + v[3].y; t23.z = v[2].z + v[3].z; t23.w = v[2].w + v[3].w;
            t45.x = v[4].x + v[5].x; t45.y = v[4].y + v[5].y; t45.z = v[4].z + v[5].z; t45.w = v[4].w + v[5].w;
            t67.x = v[6].x + v[7].x; t67.y = v[6].y + v[7].y; t67.z = v[6].z + v[7].z; t67.w = v[6].w + v[7].w;
            t03.x = t01.x + t23.x; t03.y = t01.y + t23.y; t03.z = t01.z + t23.z; t03.w = t01.w + t23.w;
            t47.x = t45.x + t67.x; t47.y = t45.y + t67.y; t47.z = t45.z + t67.z; t47.w = t45.w + t67.w;
            t.x = t03.x + t47.x; t.y = t03.y + t47.y; t.z = t03.z + t47.z; t.w = t03.w + t47.w;
            acc.x += t.x; acc.y += t.y; acc.z += t.z; acc.w += t.w;
        } else {
            // Slow path (segment boundary inside this group): per-row logic.
            #pragma unroll
            for (int j = 0; j < 8; ++j) {
                int s = braw[(r + j) * stride];
                if (s != cur) {
                    flush_acc(out, cur, lane, acc, max_seg, synced);
                    cur = s;
                    acc = make_float4(0.f, 0.f, 0.f, 0.f);
                }
                acc.x += v[j].x; acc.y += v[j].y; acc.z += v[j].z; acc.w += v[j].w;
            }
        }
    }
    // Tail (< 8 rows)
    for (; r < end; ++r) {
        int s = braw[r * stride];
        float4 vv = __ldcs(&h[(size_t)r * 32 + lane]);
        if (s != cur) {
            flush_acc(out, cur, lane, acc, max_seg, synced);
            cur = s;
            acc = make_float4(0.f, 0.f, 0.f, 0.f);
        }
        acc.x += vv.x; acc.y += vv.y; acc.z += vv.z; acc.w += vv.w;
    }
    // Final flush
    flush_acc(out, cur, lane, acc, max_seg, synced);
}

// ---------------------------------------------------------------------------
// Launch. Inputs: h_t (float32, N*FEAT) and batch (int32 or int64, N).
// Order disambiguated by element count (h_t is FEAT x larger).
// seg_sum is launched with programmatic stream serialization (PDL) so it
// overlaps the prologue's zeroing.
// ---------------------------------------------------------------------------
extern "C" void kernel_launch(void* const* d_in, const int* in_sizes, int n_in,
                              void* d_out, int out_size) {
    int hi = 0, bi = 1;
    if (n_in >= 2 && in_sizes[0] < in_sizes[1]) { hi = 1; bi = 0; }

    const float4* h        = (const float4*)d_in[hi];
    const int*    batchRaw = (const int*)d_in[bi];
    float*        out      = (float*)d_out;

    const int n_rows  = in_sizes[bi];
    const int max_seg = out_size / FEAT;

    // 1) zero output (signals PDL completion when done)
    int n4 = out_size / 4;
    prologue_kernel<<<(n4 + 255) / 256, 256>>>((float4*)d_out, n4);

    // 2) segment sum — PDL launch, overlaps with prologue
    int n_warps  = (n_rows + ROWS_PER_WARP - 1) / ROWS_PER_WARP;
    int n_blocks = (n_warps + WARPS_PER_BLOCK - 1) / WARPS_PER_BLOCK;

    cudaLaunchConfig_t cfg = {};
    cfg.gridDim  = dim3(n_blocks, 1, 1);
    cfg.blockDim = dim3(BLOCK_THREADS, 1, 1);
    cfg.dynamicSmemBytes = 0;
    cfg.stream = 0;  // legacy default stream (same as <<<>>> above)
    cudaLaunchAttribute attrs[1];
    attrs[0].id = cudaLaunchAttributeProgrammaticStreamSerialization;
    attrs[0].val.programmaticStreamSerializationAllowed = 1;
    cfg.attrs = attrs;
    cfg.numAttrs = 1;
    cudaLaunchKernelEx(&cfg, seg_sum_kernel, h, batchRaw, out, n_rows, max_seg);
}